// round 3
// baseline (speedup 1.0000x reference)
#include <cuda_runtime.h>
#include <math.h>
#include <stdint.h>

// Problem constants
#define BB 2
#define SS 576
#define FF 16
#define DD 512
#define HH 8
#define CC 64
#define MROWS (BB*SS*FF)   // 18432

// Scratch (allocation-free: __device__ globals)
__device__ float g_q[MROWS*DD];
__device__ float g_k[MROWS*DD];
__device__ float g_v[MROWS*DD];
__device__ float g_att[MROWS*DD];
__device__ int   g_frames[BB][FF];
__device__ int   g_df[BB];

__device__ __forceinline__ float to_tf32(float x) {
    float r;
    asm("cvt.rna.tf32.f32 %0, %1;" : "=f"(r) : "f"(x));
    return r;
}

// m16n8k8 tf32 MMA, fp32 accumulate. Fragment layout (lane l, g=l/4, t=l%4):
//  A(16x8): a0=A[g][t] a1=A[g+8][t] a2=A[g][t+4] a3=A[g+8][t+4]
//  B(8x8):  b0=B[t][g] b1=B[t+4][g]
//  D(16x8): d0=D[g][2t] d1=D[g][2t+1] d2=D[g+8][2t] d3=D[g+8][2t+1]
__device__ __forceinline__ void mma_tf32(float d[4], const uint32_t a[4], const uint32_t b[2]) {
    asm("mma.sync.aligned.m16n8k8.row.col.f32.tf32.tf32.f32 "
        "{%0,%1,%2,%3}, {%4,%5,%6,%7}, {%8,%9}, {%0,%1,%2,%3};"
        : "+f"(d[0]), "+f"(d[1]), "+f"(d[2]), "+f"(d[3])
        : "r"(a[0]), "r"(a[1]), "r"(a[2]), "r"(a[3]),
          "r"(b[0]), "r"(b[1]));
}

// ---------------------------------------------------------------------------
// Build kept-frame index list per batch from drop_mask (int32, shape (B, F-2))
// ---------------------------------------------------------------------------
__global__ void build_frames_kernel(const int* __restrict__ mask)
{
    if (threadIdx.x == 0 && blockIdx.x == 0) {
        for (int b = 0; b < BB; b++) {
            int n = 0;
            g_frames[b][n++] = 0;
            g_frames[b][n++] = 1;
            for (int f = 2; f < FF; f++)
                if (mask[b*(FF-2) + (f-2)] == 0) g_frames[b][n++] = f;
            g_df[b] = n;
        }
    }
}

// ---------------------------------------------------------------------------
// tf32 MMA GEMM: C[M,512] = A[M,512] @ W[512,512] (+ bias).
// Block 128x128, KC=16, 256 threads (8 warps: 4m x 2n), warp tile 32x64.
// ---------------------------------------------------------------------------
__global__ __launch_bounds__(256) void gemm_tf32_kernel(
    const float* __restrict__ A, const float* __restrict__ W,
    float* __restrict__ C, const float* __restrict__ bias)
{
    __shared__ float As[128][20];    // [m][k], pad 4 (conflict-free frag reads)
    __shared__ float Bs[16][136];    // [k][n], pad 8

    const int tid = threadIdx.x;
    const int lid = tid & 31, wid = tid >> 5;
    const int gID = lid >> 2, ct = lid & 3;
    const int warpM = wid >> 1;      // 0..3
    const int warpN = wid & 1;       // 0..1
    const int bm = blockIdx.x * 128;
    const int bn = blockIdx.y * 128;

    // Tile-load assignments (float4 granularity)
    // A tile 128x16 = 512 float4: idx -> row=idx>>2, c4=idx&3
    // B tile 16x128 = 512 float4: idx -> k=idx>>5, n4=idx&31
    const int a_row0 = tid >> 2,        a_c4 = tid & 3;
    const int a_row1 = (tid + 256) >> 2;
    const int b_k0   = tid >> 5,        b_n4 = tid & 31;
    const int b_k1   = (tid + 256) >> 5;

    const float* Ap0 = A + (size_t)(bm + a_row0) * DD + a_c4 * 4;
    const float* Ap1 = A + (size_t)(bm + a_row1) * DD + a_c4 * 4;
    const float* Bp0 = W + (size_t)b_k0 * DD + bn + b_n4 * 4;
    const float* Bp1 = W + (size_t)b_k1 * DD + bn + b_n4 * 4;

    float acc[2][8][4];
#pragma unroll
    for (int mf = 0; mf < 2; mf++)
#pragma unroll
        for (int nf = 0; nf < 8; nf++)
#pragma unroll
            for (int r = 0; r < 4; r++) acc[mf][nf][r] = 0.f;

    float4 ra0 = *(const float4*)(Ap0);
    float4 ra1 = *(const float4*)(Ap1);
    float4 rb0 = *(const float4*)(Bp0);
    float4 rb1 = *(const float4*)(Bp1);

    for (int k0 = 0; k0 < DD; k0 += 16) {
        __syncthreads();
        As[a_row0][a_c4*4+0] = to_tf32(ra0.x); As[a_row0][a_c4*4+1] = to_tf32(ra0.y);
        As[a_row0][a_c4*4+2] = to_tf32(ra0.z); As[a_row0][a_c4*4+3] = to_tf32(ra0.w);
        As[a_row1][a_c4*4+0] = to_tf32(ra1.x); As[a_row1][a_c4*4+1] = to_tf32(ra1.y);
        As[a_row1][a_c4*4+2] = to_tf32(ra1.z); As[a_row1][a_c4*4+3] = to_tf32(ra1.w);
        Bs[b_k0][b_n4*4+0] = to_tf32(rb0.x); Bs[b_k0][b_n4*4+1] = to_tf32(rb0.y);
        Bs[b_k0][b_n4*4+2] = to_tf32(rb0.z); Bs[b_k0][b_n4*4+3] = to_tf32(rb0.w);
        Bs[b_k1][b_n4*4+0] = to_tf32(rb1.x); Bs[b_k1][b_n4*4+1] = to_tf32(rb1.y);
        Bs[b_k1][b_n4*4+2] = to_tf32(rb1.z); Bs[b_k1][b_n4*4+3] = to_tf32(rb1.w);
        __syncthreads();

        if (k0 + 16 < DD) {
            ra0 = *(const float4*)(Ap0 + k0 + 16);
            ra1 = *(const float4*)(Ap1 + k0 + 16);
            rb0 = *(const float4*)(Bp0 + (size_t)(k0 + 16) * DD);
            rb1 = *(const float4*)(Bp1 + (size_t)(k0 + 16) * DD);
        }

#pragma unroll
        for (int kc = 0; kc < 16; kc += 8) {
            uint32_t afr[2][4];
#pragma unroll
            for (int mf = 0; mf < 2; mf++) {
                int m = warpM * 32 + mf * 16;
                afr[mf][0] = __float_as_uint(As[m + gID    ][kc + ct    ]);
                afr[mf][1] = __float_as_uint(As[m + gID + 8][kc + ct    ]);
                afr[mf][2] = __float_as_uint(As[m + gID    ][kc + ct + 4]);
                afr[mf][3] = __float_as_uint(As[m + gID + 8][kc + ct + 4]);
            }
#pragma unroll
            for (int nf = 0; nf < 8; nf++) {
                int n = warpN * 64 + nf * 8 + gID;
                uint32_t bfr[2];
                bfr[0] = __float_as_uint(Bs[kc + ct    ][n]);
                bfr[1] = __float_as_uint(Bs[kc + ct + 4][n]);
                mma_tf32(acc[0][nf], afr[0], bfr);
                mma_tf32(acc[1][nf], afr[1], bfr);
            }
        }
    }

    // Epilogue
#pragma unroll
    for (int mf = 0; mf < 2; mf++) {
        int r = bm + warpM * 32 + mf * 16 + gID;
#pragma unroll
        for (int nf = 0; nf < 8; nf++) {
            int cidx = bn + warpN * 64 + nf * 8 + ct * 2;
            float b0 = 0.f, b1 = 0.f;
            if (bias) { b0 = bias[cidx]; b1 = bias[cidx + 1]; }
            float2 v0 = make_float2(acc[mf][nf][0] + b0, acc[mf][nf][1] + b1);
            float2 v1 = make_float2(acc[mf][nf][2] + b0, acc[mf][nf][3] + b1);
            *(float2*)&C[(size_t)r * DD + cidx] = v0;
            *(float2*)&C[(size_t)(r + 8) * DD + cidx] = v1;
        }
    }
}

// ---------------------------------------------------------------------------
// Flash attention with tf32 MMA. 64q x 64k tiles, 128 threads (4 warps).
// Each warp owns 16 q-rows and the full 64-key range (softmax stays in-warp).
// Q fragments in registers (pre-scaled by 1/sqrt(C)); K^T and V in smem;
// P re-fragments through the K buffer (aliased).
// MODE 0 (ress): per-frame self attention. MODE 1 (resq): gathered frames.
// ---------------------------------------------------------------------------
template<int MODE>
__global__ __launch_bounds__(128) void attn_mma_kernel(
    const float* __restrict__ Qg, const float* __restrict__ Kg,
    const float* __restrict__ Vg, float* __restrict__ Og)
{
    __shared__ float KPs[64][68];   // K as [c][key]; reused as P [q][k]
    __shared__ float Vs[64][68];    // [key][c]

    const int tid = threadIdx.x;
    const int lid = tid & 31, w = tid >> 5;
    const int gID = lid >> 2, ct = lid & 3;
    const int q0 = blockIdx.x * 64;

    int b, h, f, qf, df = 1, n_tiles;
    if (MODE == 0) {
        int y = blockIdx.y;            // 0..B*(F-1)*H-1
        b = y / ((FF-1) * HH);
        int r = y % ((FF-1) * HH);
        f = 1 + r / HH;
        h = r % HH;
        qf = f;
        n_tiles = SS / 64;
    } else {
        int y = blockIdx.y;            // 0..B*H-1
        b = y >> 3;
        h = y & 7;
        qf = 0; f = 0;
        df = g_df[b];
        n_tiles = (SS / 64) * df;
    }

    // Q fragments in registers (rows w*16+gID, +8), pre-scaled by 1/8
    uint32_t qa[8][4];
    {
        const int r0 = q0 + w * 16 + gID;
        const size_t base0 = ((size_t)(b*SS + r0    ) * FF + qf) * DD + h * CC;
        const size_t base1 = ((size_t)(b*SS + r0 + 8) * FF + qf) * DD + h * CC;
#pragma unroll
        for (int kc = 0; kc < 8; kc++) {
            qa[kc][0] = __float_as_uint(to_tf32(Qg[base0 + kc*8 + ct    ] * 0.125f));
            qa[kc][1] = __float_as_uint(to_tf32(Qg[base1 + kc*8 + ct    ] * 0.125f));
            qa[kc][2] = __float_as_uint(to_tf32(Qg[base0 + kc*8 + ct + 4] * 0.125f));
            qa[kc][3] = __float_as_uint(to_tf32(Qg[base1 + kc*8 + ct + 4] * 0.125f));
        }
    }

    float o[8][4];
#pragma unroll
    for (int nf = 0; nf < 8; nf++)
#pragma unroll
        for (int r = 0; r < 4; r++) o[nf][r] = 0.f;
    float m0 = -1e30f, m1 = -1e30f, l0 = 0.f, l1 = 0.f;

    // K/V tile load assignment: 2 threads per key row, 32 c each
    const int key   = tid >> 1;
    const int chalf = (tid & 1) * 32;

    for (int kt = 0; kt < n_tiles; kt++) {
        __syncthreads();   // previous tile's P/V reads complete
        {
            int kg = kt * 64 + key;
            int sk, fk;
            if (MODE == 0) { sk = kg; fk = f; }
            else           { sk = kg / df; fk = g_frames[b][kg - sk*df]; }
            size_t krow = ((size_t)(b*SS + sk) * FF + fk) * DD + h * CC + chalf;
#pragma unroll
            for (int u = 0; u < 8; u++) {
                int c = chalf + u * 4;
                float4 tk = *(const float4*)&Kg[krow + u*4];
                KPs[c+0][key] = to_tf32(tk.x); KPs[c+1][key] = to_tf32(tk.y);
                KPs[c+2][key] = to_tf32(tk.z); KPs[c+3][key] = to_tf32(tk.w);
                float4 tv = *(const float4*)&Vg[krow + u*4];
                tv.x = to_tf32(tv.x); tv.y = to_tf32(tv.y);
                tv.z = to_tf32(tv.z); tv.w = to_tf32(tv.w);
                *(float4*)&Vs[key][c] = tv;
            }
        }
        __syncthreads();

        // S = (Q*sc) K^T, 16x64 per warp
        float s[8][4];
#pragma unroll
        for (int nf = 0; nf < 8; nf++)
#pragma unroll
            for (int r = 0; r < 4; r++) s[nf][r] = 0.f;
#pragma unroll
        for (int kc = 0; kc < 8; kc++) {
#pragma unroll
            for (int nf = 0; nf < 8; nf++) {
                uint32_t bfr[2];
                bfr[0] = __float_as_uint(KPs[kc*8 + ct    ][nf*8 + gID]);
                bfr[1] = __float_as_uint(KPs[kc*8 + ct + 4][nf*8 + gID]);
                mma_tf32(s[nf], qa[kc], bfr);
            }
        }

        // Online softmax: rows gID (regs 0,1) and gID+8 (regs 2,3)
        float mx0 = -1e30f, mx1 = -1e30f;
#pragma unroll
        for (int nf = 0; nf < 8; nf++) {
            mx0 = fmaxf(mx0, fmaxf(s[nf][0], s[nf][1]));
            mx1 = fmaxf(mx1, fmaxf(s[nf][2], s[nf][3]));
        }
        mx0 = fmaxf(mx0, __shfl_xor_sync(0xffffffffu, mx0, 1));
        mx0 = fmaxf(mx0, __shfl_xor_sync(0xffffffffu, mx0, 2));
        mx1 = fmaxf(mx1, __shfl_xor_sync(0xffffffffu, mx1, 1));
        mx1 = fmaxf(mx1, __shfl_xor_sync(0xffffffffu, mx1, 2));

        float m0n = fmaxf(m0, mx0), m1n = fmaxf(m1, mx1);
        float a0 = __expf(m0 - m0n), a1 = __expf(m1 - m1n);
        float s0 = 0.f, s1 = 0.f;
#pragma unroll
        for (int nf = 0; nf < 8; nf++) {
            s[nf][0] = __expf(s[nf][0] - m0n);
            s[nf][1] = __expf(s[nf][1] - m0n);
            s[nf][2] = __expf(s[nf][2] - m1n);
            s[nf][3] = __expf(s[nf][3] - m1n);
            s0 += s[nf][0] + s[nf][1];
            s1 += s[nf][2] + s[nf][3];
        }
        s0 += __shfl_xor_sync(0xffffffffu, s0, 1);
        s0 += __shfl_xor_sync(0xffffffffu, s0, 2);
        s1 += __shfl_xor_sync(0xffffffffu, s1, 1);
        s1 += __shfl_xor_sync(0xffffffffu, s1, 2);
        l0 = l0 * a0 + s0; m0 = m0n;
        l1 = l1 * a1 + s1; m1 = m1n;
#pragma unroll
        for (int nf = 0; nf < 8; nf++) {
            o[nf][0] *= a0; o[nf][1] *= a0;
            o[nf][2] *= a1; o[nf][3] *= a1;
        }

        __syncthreads();   // all warps finished reading KPs as K

        // Store P (tf32) into KPs as [q][k]; each warp writes its own rows.
        const int pr0 = w * 16 + gID, pr1 = pr0 + 8;
#pragma unroll
        for (int nf = 0; nf < 8; nf++) {
            int col = nf * 8 + ct * 2;
            float2 v0 = make_float2(to_tf32(s[nf][0]), to_tf32(s[nf][1]));
            float2 v1 = make_float2(to_tf32(s[nf][2]), to_tf32(s[nf][3]));
            *(float2*)&KPs[pr0][col] = v0;
            *(float2*)&KPs[pr1][col] = v1;
        }
        // No sync needed: each warp reads back only the rows it wrote.

        // O += P @ V
#pragma unroll
        for (int kc = 0; kc < 8; kc++) {
            uint32_t pa[4];
            pa[0] = __float_as_uint(KPs[pr0][kc*8 + ct    ]);
            pa[1] = __float_as_uint(KPs[pr1][kc*8 + ct    ]);
            pa[2] = __float_as_uint(KPs[pr0][kc*8 + ct + 4]);
            pa[3] = __float_as_uint(KPs[pr1][kc*8 + ct + 4]);
#pragma unroll
            for (int nf = 0; nf < 8; nf++) {
                uint32_t bfr[2];
                bfr[0] = __float_as_uint(Vs[kc*8 + ct    ][nf*8 + gID]);
                bfr[1] = __float_as_uint(Vs[kc*8 + ct + 4][nf*8 + gID]);
                mma_tf32(o[nf], pa, bfr);
            }
        }
    }

    // Epilogue: normalize and write to output frame slot
    const int of = (MODE == 0) ? f : 0;
    const float inv0 = 1.0f / l0, inv1 = 1.0f / l1;
    const int r0 = q0 + w * 16 + gID;
    const size_t ob0 = ((size_t)(b*SS + r0    ) * FF + of) * DD + h * CC;
    const size_t ob1 = ((size_t)(b*SS + r0 + 8) * FF + of) * DD + h * CC;
#pragma unroll
    for (int nf = 0; nf < 8; nf++) {
        int col = nf * 8 + ct * 2;
        *(float2*)&Og[ob0 + col] = make_float2(o[nf][0] * inv0, o[nf][1] * inv0);
        *(float2*)&Og[ob1 + col] = make_float2(o[nf][2] * inv1, o[nf][3] * inv1);
    }
}

// ---------------------------------------------------------------------------
// kernel_launch: graph-capturable sequence on the default stream.
// ---------------------------------------------------------------------------
extern "C" void kernel_launch(void* const* d_in, const int* in_sizes, int n_in,
                              void* d_out, int out_size)
{
    const float* x    = (const float*)d_in[0];
    const int*   mask = (const int*)  d_in[1];   // drop_mask (int32)
    const float* Wq   = (const float*)d_in[2];
    const float* Wk   = (const float*)d_in[3];
    const float* Wv   = (const float*)d_in[4];
    const float* Wout = (const float*)d_in[5];
    const float* bout = (const float*)d_in[6];
    float* out = (float*)d_out;

    float *q, *k, *v, *att;
    cudaGetSymbolAddress((void**)&q,   g_q);
    cudaGetSymbolAddress((void**)&k,   g_k);
    cudaGetSymbolAddress((void**)&v,   g_v);
    cudaGetSymbolAddress((void**)&att, g_att);

    build_frames_kernel<<<1, 32>>>(mask);

    dim3 ggrid(MROWS / 128, DD / 128);   // (144, 4)
    gemm_tf32_kernel<<<ggrid, 256>>>(x, Wq, q, nullptr);
    gemm_tf32_kernel<<<ggrid, 256>>>(x, Wk, k, nullptr);
    gemm_tf32_kernel<<<ggrid, 256>>>(x, Wv, v, nullptr);

    // ress: per-frame self attention, frames 1..15
    attn_mma_kernel<0><<<dim3(SS / 64, BB * (FF-1) * HH), 128>>>(q, k, v, att);
    // resq: frame-0 queries over gathered key/value frames
    attn_mma_kernel<1><<<dim3(SS / 64, BB * HH), 128>>>(q, k, v, att);

    // output projection + bias
    gemm_tf32_kernel<<<ggrid, 256>>>(att, Wout, out, bout);
}

// round 4
// speedup vs baseline: 1.1534x; 1.1534x over previous
#include <cuda_runtime.h>
#include <math.h>
#include <stdint.h>

// Problem constants
#define BB 2
#define SS 576
#define FF 16
#define DD 512
#define HH 8
#define CC 64
#define MROWS (BB*SS*FF)   // 18432
#define NSPLIT 8

// Scratch (allocation-free: __device__ globals)
__device__ float g_q[MROWS*DD];
__device__ float g_k[MROWS*DD];
__device__ float g_v[MROWS*DD];
__device__ float g_att[MROWS*DD];
__device__ float g_opart[NSPLIT*BB*HH*SS*CC];   // resq split partials (normalized)
__device__ float g_ml[NSPLIT*BB*HH*SS*2];       // per-row (m, l) per split
__device__ int   g_frames[BB][FF];
__device__ int   g_df[BB];

__device__ __forceinline__ float to_tf32(float x) {
    float r;
    asm("cvt.rna.tf32.f32 %0, %1;" : "=f"(r) : "f"(x));
    return r;
}

// m16n8k8 tf32 MMA, fp32 accumulate. (lane l, g=l/4, t=l%4):
//  A(16x8): a0=A[g][t] a1=A[g+8][t] a2=A[g][t+4] a3=A[g+8][t+4]
//  B(8x8):  b0=B[t][g] b1=B[t+4][g]
//  D(16x8): d0=D[g][2t] d1=D[g][2t+1] d2=D[g+8][2t] d3=D[g+8][2t+1]
__device__ __forceinline__ void mma_tf32(float d[4], const uint32_t a[4], const uint32_t b[2]) {
    asm("mma.sync.aligned.m16n8k8.row.col.f32.tf32.tf32.f32 "
        "{%0,%1,%2,%3}, {%4,%5,%6,%7}, {%8,%9}, {%0,%1,%2,%3};"
        : "+f"(d[0]), "+f"(d[1]), "+f"(d[2]), "+f"(d[3])
        : "r"(a[0]), "r"(a[1]), "r"(a[2]), "r"(a[3]),
          "r"(b[0]), "r"(b[1]));
}

// ---------------------------------------------------------------------------
__global__ void build_frames_kernel(const int* __restrict__ mask)
{
    if (threadIdx.x == 0 && blockIdx.x == 0) {
        for (int b = 0; b < BB; b++) {
            int n = 0;
            g_frames[b][n++] = 0;
            g_frames[b][n++] = 1;
            for (int f = 2; f < FF; f++)
                if (mask[b*(FF-2) + (f-2)] == 0) g_frames[b][n++] = f;
            g_df[b] = n;
        }
    }
}

// ---------------------------------------------------------------------------
// tf32 MMA GEMM, z-fused over up to 3 weight matrices sharing the same A.
// Block 128x128, KC=16, 256 threads (8 warps: 4m x 2n), warp tile 32x64.
// ---------------------------------------------------------------------------
__global__ __launch_bounds__(256) void gemm_tf32_kernel(
    const float* __restrict__ A,
    const float* __restrict__ W0, const float* __restrict__ W1, const float* __restrict__ W2,
    float* __restrict__ C0, float* __restrict__ C1, float* __restrict__ C2,
    const float* __restrict__ bias)
{
    __shared__ float As[128][20];    // [m][k], pad 4
    __shared__ float Bs[16][136];    // [k][n], pad 8

    const int z = blockIdx.z;
    const float* W = (z == 0) ? W0 : (z == 1) ? W1 : W2;
    float* C       = (z == 0) ? C0 : (z == 1) ? C1 : C2;

    const int tid = threadIdx.x;
    const int lid = tid & 31, wid = tid >> 5;
    const int gID = lid >> 2, ct = lid & 3;
    const int warpM = wid >> 1;
    const int warpN = wid & 1;
    const int bm = blockIdx.x * 128;
    const int bn = blockIdx.y * 128;

    const int a_row0 = tid >> 2,        a_c4 = tid & 3;
    const int a_row1 = (tid + 256) >> 2;
    const int b_k0   = tid >> 5,        b_n4 = tid & 31;
    const int b_k1   = (tid + 256) >> 5;

    const float* Ap0 = A + (size_t)(bm + a_row0) * DD + a_c4 * 4;
    const float* Ap1 = A + (size_t)(bm + a_row1) * DD + a_c4 * 4;
    const float* Bp0 = W + (size_t)b_k0 * DD + bn + b_n4 * 4;
    const float* Bp1 = W + (size_t)b_k1 * DD + bn + b_n4 * 4;

    float acc[2][8][4];
#pragma unroll
    for (int mf = 0; mf < 2; mf++)
#pragma unroll
        for (int nf = 0; nf < 8; nf++)
#pragma unroll
            for (int r = 0; r < 4; r++) acc[mf][nf][r] = 0.f;

    float4 ra0 = *(const float4*)(Ap0);
    float4 ra1 = *(const float4*)(Ap1);
    float4 rb0 = *(const float4*)(Bp0);
    float4 rb1 = *(const float4*)(Bp1);

    for (int k0 = 0; k0 < DD; k0 += 16) {
        __syncthreads();
        {
            float4 c0 = make_float4(to_tf32(ra0.x), to_tf32(ra0.y), to_tf32(ra0.z), to_tf32(ra0.w));
            float4 c1 = make_float4(to_tf32(ra1.x), to_tf32(ra1.y), to_tf32(ra1.z), to_tf32(ra1.w));
            float4 c2 = make_float4(to_tf32(rb0.x), to_tf32(rb0.y), to_tf32(rb0.z), to_tf32(rb0.w));
            float4 c3 = make_float4(to_tf32(rb1.x), to_tf32(rb1.y), to_tf32(rb1.z), to_tf32(rb1.w));
            *(float4*)&As[a_row0][a_c4*4] = c0;
            *(float4*)&As[a_row1][a_c4*4] = c1;
            *(float4*)&Bs[b_k0][b_n4*4]   = c2;
            *(float4*)&Bs[b_k1][b_n4*4]   = c3;
        }
        __syncthreads();

        if (k0 + 16 < DD) {
            ra0 = *(const float4*)(Ap0 + k0 + 16);
            ra1 = *(const float4*)(Ap1 + k0 + 16);
            rb0 = *(const float4*)(Bp0 + (size_t)(k0 + 16) * DD);
            rb1 = *(const float4*)(Bp1 + (size_t)(k0 + 16) * DD);
        }

#pragma unroll
        for (int kc = 0; kc < 16; kc += 8) {
            uint32_t afr[2][4];
#pragma unroll
            for (int mf = 0; mf < 2; mf++) {
                int m = warpM * 32 + mf * 16;
                afr[mf][0] = __float_as_uint(As[m + gID    ][kc + ct    ]);
                afr[mf][1] = __float_as_uint(As[m + gID + 8][kc + ct    ]);
                afr[mf][2] = __float_as_uint(As[m + gID    ][kc + ct + 4]);
                afr[mf][3] = __float_as_uint(As[m + gID + 8][kc + ct + 4]);
            }
#pragma unroll
            for (int nf = 0; nf < 8; nf++) {
                int n = warpN * 64 + nf * 8 + gID;
                uint32_t bfr[2];
                bfr[0] = __float_as_uint(Bs[kc + ct    ][n]);
                bfr[1] = __float_as_uint(Bs[kc + ct + 4][n]);
                mma_tf32(acc[0][nf], afr[0], bfr);
                mma_tf32(acc[1][nf], afr[1], bfr);
            }
        }
    }

#pragma unroll
    for (int mf = 0; mf < 2; mf++) {
        int r = bm + warpM * 32 + mf * 16 + gID;
#pragma unroll
        for (int nf = 0; nf < 8; nf++) {
            int cidx = bn + warpN * 64 + nf * 8 + ct * 2;
            float b0 = 0.f, b1 = 0.f;
            if (bias) { b0 = bias[cidx]; b1 = bias[cidx + 1]; }
            float2 v0 = make_float2(acc[mf][nf][0] + b0, acc[mf][nf][1] + b1);
            float2 v1 = make_float2(acc[mf][nf][2] + b0, acc[mf][nf][3] + b1);
            *(float2*)&C[(size_t)r * DD + cidx] = v0;
            *(float2*)&C[(size_t)(r + 8) * DD + cidx] = v1;
        }
    }
}

// ---------------------------------------------------------------------------
// Flash attention, tf32 MMA, pipelined.
// 64q tiles, 128 threads (4 warps, 16 q-rows each, full key range per warp).
// Ping-pong smem K/V buffers (dynamic); next-K prefetched during S, next-V
// during PV. P aliases the current K buffer. Q frags in regs (pre-scaled).
// MODE 0 (ress): direct output. MODE 1 (resq): split-KV over blockIdx.z,
// writes normalized partials + (m,l) for later merge.
// smem layout: Ks[2][64][68], Vs[2][64][72]  (71680 bytes)
// ---------------------------------------------------------------------------
#define KS_STRIDE 68
#define VS_STRIDE 72
#define KS_BUF (64*KS_STRIDE)
#define VS_BUF (64*VS_STRIDE)
#define SMEM_ATTN ((2*KS_BUF + 2*VS_BUF)*4)

template<int MODE>
__global__ __launch_bounds__(128) void attn_mma_kernel(
    const float* __restrict__ Qg, const float* __restrict__ Kg,
    const float* __restrict__ Vg, float* __restrict__ Og,
    float* __restrict__ Opart, float* __restrict__ Ml)
{
    extern __shared__ float sm[];
    float* Ksm = sm;                // [2][64][68]
    float* Vsm = sm + 2*KS_BUF;     // [2][64][72]

    const int tid = threadIdx.x;
    const int lid = tid & 31, w = tid >> 5;
    const int gID = lid >> 2, ct = lid & 3;
    const int q0 = blockIdx.x * 64;

    int b, h, f, qf, df = 1, t0, t1;
    if (MODE == 0) {
        int y = blockIdx.y;
        b = y / ((FF-1) * HH);
        int r = y % ((FF-1) * HH);
        f = 1 + r / HH;
        h = r % HH;
        qf = f;
        t0 = 0; t1 = SS / 64;
    } else {
        int y = blockIdx.y;
        b = y >> 3;
        h = y & 7;
        qf = 0; f = 0;
        df = g_df[b];
        int ntot = (SS / 64) * df;
        int sp = blockIdx.z;
        t0 = sp * ntot / NSPLIT;
        t1 = (sp + 1) * ntot / NSPLIT;
    }

    // Q fragments in registers (rows w*16+gID, +8), pre-scaled by 1/8
    uint32_t qa[8][4];
    {
        const int r0 = q0 + w * 16 + gID;
        const size_t base0 = ((size_t)(b*SS + r0    ) * FF + qf) * DD + h * CC;
        const size_t base1 = ((size_t)(b*SS + r0 + 8) * FF + qf) * DD + h * CC;
#pragma unroll
        for (int kc = 0; kc < 8; kc++) {
            qa[kc][0] = __float_as_uint(to_tf32(Qg[base0 + kc*8 + ct    ] * 0.125f));
            qa[kc][1] = __float_as_uint(to_tf32(Qg[base1 + kc*8 + ct    ] * 0.125f));
            qa[kc][2] = __float_as_uint(to_tf32(Qg[base0 + kc*8 + ct + 4] * 0.125f));
            qa[kc][3] = __float_as_uint(to_tf32(Qg[base1 + kc*8 + ct + 4] * 0.125f));
        }
    }

    float o[8][4];
#pragma unroll
    for (int nf = 0; nf < 8; nf++)
#pragma unroll
        for (int r = 0; r < 4; r++) o[nf][r] = 0.f;
    float m0 = -1e30f, m1 = -1e30f, l0 = 0.f, l1 = 0.f;

    // K/V tile load assignment: key = tid&63 (phase-friendly), half of c
    const int key   = tid & 63;
    const int chalf = (tid >> 6) * 32;

    // Global row base for a tile index kt (recomputed per use)
    auto row_of = [&](int kt) -> size_t {
        int kg = kt * 64 + key;
        int sk, fk;
        if (MODE == 0) { sk = kg; fk = f; }
        else           { sk = kg / df; fk = g_frames[b][kg - sk*df]; }
        return ((size_t)(b*SS + sk) * FF + fk) * DD + h * CC + chalf;
    };

    float4 kreg[8], vreg[8];
    {
        size_t r = row_of(t0);
#pragma unroll
        for (int u = 0; u < 8; u++) kreg[u] = *(const float4*)&Kg[r + u*4];
#pragma unroll
        for (int u = 0; u < 8; u++) vreg[u] = *(const float4*)&Vg[r + u*4];
    }

    const int pr0 = w * 16 + gID, pr1 = pr0 + 8;

    for (int kt = t0; kt < t1; kt++) {
        const int cur = kt & 1;
        float* Kb = Ksm + cur * KS_BUF;
        float* Vb = Vsm + cur * VS_BUF;

        // Store prefetched tile to smem (cvt to tf32, vectorized)
        {
            float* kd = Kb + key * KS_STRIDE + chalf;
            float* vd = Vb + key * VS_STRIDE + chalf;
#pragma unroll
            for (int u = 0; u < 8; u++) {
                float4 kc4 = make_float4(to_tf32(kreg[u].x), to_tf32(kreg[u].y),
                                         to_tf32(kreg[u].z), to_tf32(kreg[u].w));
                *(float4*)(kd + u*4) = kc4;
            }
#pragma unroll
            for (int u = 0; u < 8; u++) {
                float4 vc4 = make_float4(to_tf32(vreg[u].x), to_tf32(vreg[u].y),
                                         to_tf32(vreg[u].z), to_tf32(vreg[u].w));
                *(float4*)(vd + u*4) = vc4;
            }
        }
        __syncthreads();

        // Prefetch next K tile (latency hidden by S + softmax)
        if (kt + 1 < t1) {
            size_t r = row_of(kt + 1);
#pragma unroll
            for (int u = 0; u < 8; u++) kreg[u] = *(const float4*)&Kg[r + u*4];
        }

        // S = (Q*sc) K^T : A=Q rows, B=K^T (k=c, n=key); K stored [key][c]
        float s[8][4];
#pragma unroll
        for (int nf = 0; nf < 8; nf++)
#pragma unroll
            for (int r = 0; r < 4; r++) s[nf][r] = 0.f;
#pragma unroll
        for (int kc = 0; kc < 8; kc++) {
#pragma unroll
            for (int nf = 0; nf < 8; nf++) {
                uint32_t bfr[2];
                bfr[0] = __float_as_uint(Kb[(nf*8 + gID) * KS_STRIDE + kc*8 + ct    ]);
                bfr[1] = __float_as_uint(Kb[(nf*8 + gID) * KS_STRIDE + kc*8 + ct + 4]);
                mma_tf32(s[nf], qa[kc], bfr);
            }
        }

        // Online softmax (rows gID -> regs 0,1 and gID+8 -> regs 2,3)
        float mx0 = -1e30f, mx1 = -1e30f;
#pragma unroll
        for (int nf = 0; nf < 8; nf++) {
            mx0 = fmaxf(mx0, fmaxf(s[nf][0], s[nf][1]));
            mx1 = fmaxf(mx1, fmaxf(s[nf][2], s[nf][3]));
        }
        mx0 = fmaxf(mx0, __shfl_xor_sync(0xffffffffu, mx0, 1));
        mx0 = fmaxf(mx0, __shfl_xor_sync(0xffffffffu, mx0, 2));
        mx1 = fmaxf(mx1, __shfl_xor_sync(0xffffffffu, mx1, 1));
        mx1 = fmaxf(mx1, __shfl_xor_sync(0xffffffffu, mx1, 2));

        float m0n = fmaxf(m0, mx0), m1n = fmaxf(m1, mx1);
        float a0 = __expf(m0 - m0n), a1 = __expf(m1 - m1n);
        float s0 = 0.f, s1 = 0.f;
#pragma unroll
        for (int nf = 0; nf < 8; nf++) {
            s[nf][0] = __expf(s[nf][0] - m0n);
            s[nf][1] = __expf(s[nf][1] - m0n);
            s[nf][2] = __expf(s[nf][2] - m1n);
            s[nf][3] = __expf(s[nf][3] - m1n);
            s0 += s[nf][0] + s[nf][1];
            s1 += s[nf][2] + s[nf][3];
        }
        s0 += __shfl_xor_sync(0xffffffffu, s0, 1);
        s0 += __shfl_xor_sync(0xffffffffu, s0, 2);
        s1 += __shfl_xor_sync(0xffffffffu, s1, 1);
        s1 += __shfl_xor_sync(0xffffffffu, s1, 2);
        l0 = l0 * a0 + s0; m0 = m0n;
        l1 = l1 * a1 + s1; m1 = m1n;
#pragma unroll
        for (int nf = 0; nf < 8; nf++) {
            o[nf][0] *= a0; o[nf][1] *= a0;
            o[nf][2] *= a1; o[nf][3] *= a1;
        }

        __syncthreads();   // all warps done reading Kb as K

        // Store P (tf32) into Kb as [q][key]; own rows only
#pragma unroll
        for (int nf = 0; nf < 8; nf++) {
            int col = nf * 8 + ct * 2;
            *(float2*)&Kb[pr0 * KS_STRIDE + col] =
                make_float2(to_tf32(s[nf][0]), to_tf32(s[nf][1]));
            *(float2*)&Kb[pr1 * KS_STRIDE + col] =
                make_float2(to_tf32(s[nf][2]), to_tf32(s[nf][3]));
        }

        // Prefetch next V tile (latency hidden by PV)
        if (kt + 1 < t1) {
            size_t r = row_of(kt + 1);
#pragma unroll
            for (int u = 0; u < 8; u++) vreg[u] = *(const float4*)&Vg[r + u*4];
        }

        // O += P @ V : A=P rows, B=V (k=key, n=c); V stored [key][c]
#pragma unroll
        for (int kc = 0; kc < 8; kc++) {
            uint32_t pa[4];
            pa[0] = __float_as_uint(Kb[pr0 * KS_STRIDE + kc*8 + ct    ]);
            pa[1] = __float_as_uint(Kb[pr1 * KS_STRIDE + kc*8 + ct    ]);
            pa[2] = __float_as_uint(Kb[pr0 * KS_STRIDE + kc*8 + ct + 4]);
            pa[3] = __float_as_uint(Kb[pr1 * KS_STRIDE + kc*8 + ct + 4]);
#pragma unroll
            for (int nf = 0; nf < 8; nf++) {
                uint32_t bfr[2];
                bfr[0] = __float_as_uint(Vb[(kc*8 + ct    ) * VS_STRIDE + nf*8 + gID]);
                bfr[1] = __float_as_uint(Vb[(kc*8 + ct + 4) * VS_STRIDE + nf*8 + gID]);
                mma_tf32(o[nf], pa, bfr);
            }
        }
    }

    // Epilogue
    const float inv0 = 1.0f / l0, inv1 = 1.0f / l1;
    const int r0 = q0 + w * 16 + gID;
    if (MODE == 0) {
        const size_t ob0 = ((size_t)(b*SS + r0    ) * FF + f) * DD + h * CC;
        const size_t ob1 = ((size_t)(b*SS + r0 + 8) * FF + f) * DD + h * CC;
#pragma unroll
        for (int nf = 0; nf < 8; nf++) {
            int col = nf * 8 + ct * 2;
            *(float2*)&Og[ob0 + col] = make_float2(o[nf][0] * inv0, o[nf][1] * inv0);
            *(float2*)&Og[ob1 + col] = make_float2(o[nf][2] * inv1, o[nf][3] * inv1);
        }
    } else {
        const int y = blockIdx.y, sp = blockIdx.z;
        const size_t pb0 = ((size_t)(sp*(BB*HH) + y) * SS + r0    ) * CC;
        const size_t pb1 = ((size_t)(sp*(BB*HH) + y) * SS + r0 + 8) * CC;
#pragma unroll
        for (int nf = 0; nf < 8; nf++) {
            int col = nf * 8 + ct * 2;
            *(float2*)&Opart[pb0 + col] = make_float2(o[nf][0] * inv0, o[nf][1] * inv0);
            *(float2*)&Opart[pb1 + col] = make_float2(o[nf][2] * inv1, o[nf][3] * inv1);
        }
        if (ct == 0) {
            size_t mb = ((size_t)(sp*(BB*HH) + y) * SS + r0) * 2;
            Ml[mb + 0] = m0; Ml[mb + 1] = l0;
            Ml[mb + CC/4] = 0.f; // placeholder avoided; see below
        }
        if (ct == 0) {
            size_t mb1 = ((size_t)(sp*(BB*HH) + y) * SS + r0 + 8) * 2;
            Ml[mb1 + 0] = m1; Ml[mb1 + 1] = l1;
        }
    }
}

// ---------------------------------------------------------------------------
// Merge resq split partials into g_att frame 0.
// One thread per (y, q, c4): float4 over C.
// ---------------------------------------------------------------------------
__global__ __launch_bounds__(256) void merge_resq_kernel(float* __restrict__ att)
{
    int idx = blockIdx.x * 256 + threadIdx.x;           // over 16*576*16
    if (idx >= BB*HH*SS*(CC/4)) return;
    int c4 = idx & 15;
    int q  = (idx >> 4) % SS;
    int y  = idx / (16 * SS);

    float m[NSPLIT], l[NSPLIT];
    float mmax = -1e30f;
#pragma unroll
    for (int s = 0; s < NSPLIT; s++) {
        size_t mb = ((size_t)(s*(BB*HH) + y) * SS + q) * 2;
        m[s] = g_ml[mb]; l[s] = g_ml[mb + 1];
        mmax = fmaxf(mmax, m[s]);
    }
    float4 acc = make_float4(0.f, 0.f, 0.f, 0.f);
    float wsum = 0.f;
#pragma unroll
    for (int s = 0; s < NSPLIT; s++) {
        float wgt = __expf(m[s] - mmax) * l[s];
        const float4 ov = *(const float4*)&g_opart[(((size_t)(s*(BB*HH) + y) * SS + q) * CC) + c4*4];
        acc.x += wgt * ov.x; acc.y += wgt * ov.y;
        acc.z += wgt * ov.z; acc.w += wgt * ov.w;
        wsum += wgt;
    }
    float inv = 1.0f / wsum;
    int b = y >> 3, h = y & 7;
    float4 r = make_float4(acc.x*inv, acc.y*inv, acc.z*inv, acc.w*inv);
    *(float4*)&att[((size_t)(b*SS + q) * FF + 0) * DD + h*CC + c4*4] = r;
}

// ---------------------------------------------------------------------------
extern "C" void kernel_launch(void* const* d_in, const int* in_sizes, int n_in,
                              void* d_out, int out_size)
{
    const float* x    = (const float*)d_in[0];
    const int*   mask = (const int*)  d_in[1];
    const float* Wq   = (const float*)d_in[2];
    const float* Wk   = (const float*)d_in[3];
    const float* Wv   = (const float*)d_in[4];
    const float* Wout = (const float*)d_in[5];
    const float* bout = (const float*)d_in[6];
    float* out = (float*)d_out;

    float *q, *k, *v, *att, *opart, *ml;
    cudaGetSymbolAddress((void**)&q,     g_q);
    cudaGetSymbolAddress((void**)&k,     g_k);
    cudaGetSymbolAddress((void**)&v,     g_v);
    cudaGetSymbolAddress((void**)&att,   g_att);
    cudaGetSymbolAddress((void**)&opart, g_opart);
    cudaGetSymbolAddress((void**)&ml,    g_ml);

    static bool attr_set = false;
    if (!attr_set) {
        cudaFuncSetAttribute(attn_mma_kernel<0>,
            cudaFuncAttributeMaxDynamicSharedMemorySize, SMEM_ATTN);
        cudaFuncSetAttribute(attn_mma_kernel<1>,
            cudaFuncAttributeMaxDynamicSharedMemorySize, SMEM_ATTN);
        attr_set = true;
    }

    build_frames_kernel<<<1, 32>>>(mask);

    // Fused QKV projections (grid.z selects weight)
    gemm_tf32_kernel<<<dim3(MROWS/128, DD/128, 3), 256>>>(
        x, Wq, Wk, Wv, q, k, v, nullptr);

    // ress: per-frame self attention, frames 1..15
    attn_mma_kernel<0><<<dim3(SS/64, BB*(FF-1)*HH, 1), 128, SMEM_ATTN>>>(
        q, k, v, att, nullptr, nullptr);
    // resq: split-KV over NSPLIT
    attn_mma_kernel<1><<<dim3(SS/64, BB*HH, NSPLIT), 128, SMEM_ATTN>>>(
        q, k, v, att, opart, ml);
    merge_resq_kernel<<<(BB*HH*SS*(CC/4) + 255)/256, 256>>>(att);

    // Output projection + bias
    gemm_tf32_kernel<<<dim3(MROWS/128, DD/128, 1), 256>>>(
        att, Wout, Wout, Wout, out, out, out, bout);
}

// round 5
// speedup vs baseline: 1.1542x; 1.0007x over previous
#include <cuda_runtime.h>
#include <math.h>
#include <stdint.h>

// Problem constants
#define BB 2
#define SS 576
#define FF 16
#define DD 512
#define HH 8
#define CC 64
#define MROWS (BB*SS*FF)   // 18432
#define NSPLIT 8

// Scratch (allocation-free: __device__ globals)
__device__ float g_q[MROWS*DD];
__device__ float g_k[MROWS*DD];
__device__ float g_v[MROWS*DD];
__device__ float g_att[MROWS*DD];
__device__ float g_opart[NSPLIT*BB*HH*SS*CC];   // resq split partials (normalized)
__device__ float g_ml[NSPLIT*BB*HH*SS*2];       // per-row (m, l) per split
__device__ int   g_frames[BB][FF];
__device__ int   g_df[BB];

__device__ __forceinline__ float to_tf32(float x) {
    float r;
    asm("cvt.rna.tf32.f32 %0, %1;" : "=f"(r) : "f"(x));
    return r;
}

// m16n8k8 tf32 MMA, fp32 accumulate. (lane l, g=l/4, t=l%4):
//  A(16x8): a0=A[g][t] a1=A[g+8][t] a2=A[g][t+4] a3=A[g+8][t+4]
//  B(8x8):  b0=B[t][g] b1=B[t+4][g]
//  D(16x8): d0=D[g][2t] d1=D[g][2t+1] d2=D[g+8][2t] d3=D[g+8][2t+1]
__device__ __forceinline__ void mma_tf32(float d[4], const uint32_t a[4], const uint32_t b[2]) {
    asm("mma.sync.aligned.m16n8k8.row.col.f32.tf32.tf32.f32 "
        "{%0,%1,%2,%3}, {%4,%5,%6,%7}, {%8,%9}, {%0,%1,%2,%3};"
        : "+f"(d[0]), "+f"(d[1]), "+f"(d[2]), "+f"(d[3])
        : "r"(a[0]), "r"(a[1]), "r"(a[2]), "r"(a[3]),
          "r"(b[0]), "r"(b[1]));
}

// ---------------------------------------------------------------------------
__global__ void build_frames_kernel(const int* __restrict__ mask)
{
    if (threadIdx.x == 0 && blockIdx.x == 0) {
        for (int b = 0; b < BB; b++) {
            int n = 0;
            g_frames[b][n++] = 0;
            g_frames[b][n++] = 1;
            for (int f = 2; f < FF; f++)
                if (mask[b*(FF-2) + (f-2)] == 0) g_frames[b][n++] = f;
            g_df[b] = n;
        }
    }
}

// ---------------------------------------------------------------------------
// tf32 MMA GEMM, z-fused over up to 3 weight matrices sharing the same A.
// Block 128x128, KC=16, 256 threads (8 warps: 4m x 2n), warp tile 32x64.
// ---------------------------------------------------------------------------
__global__ __launch_bounds__(256) void gemm_tf32_kernel(
    const float* __restrict__ A,
    const float* __restrict__ W0, const float* __restrict__ W1, const float* __restrict__ W2,
    float* __restrict__ C0, float* __restrict__ C1, float* __restrict__ C2,
    const float* __restrict__ bias)
{
    __shared__ float As[128][20];    // [m][k], pad 4
    __shared__ float Bs[16][136];    // [k][n], pad 8

    const int z = blockIdx.z;
    const float* W = (z == 0) ? W0 : (z == 1) ? W1 : W2;
    float* C       = (z == 0) ? C0 : (z == 1) ? C1 : C2;

    const int tid = threadIdx.x;
    const int lid = tid & 31, wid = tid >> 5;
    const int gID = lid >> 2, ct = lid & 3;
    const int warpM = wid >> 1;
    const int warpN = wid & 1;
    const int bm = blockIdx.x * 128;
    const int bn = blockIdx.y * 128;

    const int a_row0 = tid >> 2,        a_c4 = tid & 3;
    const int a_row1 = (tid + 256) >> 2;
    const int b_k0   = tid >> 5,        b_n4 = tid & 31;
    const int b_k1   = (tid + 256) >> 5;

    const float* Ap0 = A + (size_t)(bm + a_row0) * DD + a_c4 * 4;
    const float* Ap1 = A + (size_t)(bm + a_row1) * DD + a_c4 * 4;
    const float* Bp0 = W + (size_t)b_k0 * DD + bn + b_n4 * 4;
    const float* Bp1 = W + (size_t)b_k1 * DD + bn + b_n4 * 4;

    float acc[2][8][4];
#pragma unroll
    for (int mf = 0; mf < 2; mf++)
#pragma unroll
        for (int nf = 0; nf < 8; nf++)
#pragma unroll
            for (int r = 0; r < 4; r++) acc[mf][nf][r] = 0.f;

    float4 ra0 = *(const float4*)(Ap0);
    float4 ra1 = *(const float4*)(Ap1);
    float4 rb0 = *(const float4*)(Bp0);
    float4 rb1 = *(const float4*)(Bp1);

    for (int k0 = 0; k0 < DD; k0 += 16) {
        __syncthreads();
        {
            float4 c0 = make_float4(to_tf32(ra0.x), to_tf32(ra0.y), to_tf32(ra0.z), to_tf32(ra0.w));
            float4 c1 = make_float4(to_tf32(ra1.x), to_tf32(ra1.y), to_tf32(ra1.z), to_tf32(ra1.w));
            float4 c2 = make_float4(to_tf32(rb0.x), to_tf32(rb0.y), to_tf32(rb0.z), to_tf32(rb0.w));
            float4 c3 = make_float4(to_tf32(rb1.x), to_tf32(rb1.y), to_tf32(rb1.z), to_tf32(rb1.w));
            *(float4*)&As[a_row0][a_c4*4] = c0;
            *(float4*)&As[a_row1][a_c4*4] = c1;
            *(float4*)&Bs[b_k0][b_n4*4]   = c2;
            *(float4*)&Bs[b_k1][b_n4*4]   = c3;
        }
        __syncthreads();

        if (k0 + 16 < DD) {
            ra0 = *(const float4*)(Ap0 + k0 + 16);
            ra1 = *(const float4*)(Ap1 + k0 + 16);
            rb0 = *(const float4*)(Bp0 + (size_t)(k0 + 16) * DD);
            rb1 = *(const float4*)(Bp1 + (size_t)(k0 + 16) * DD);
        }

#pragma unroll
        for (int kc = 0; kc < 16; kc += 8) {
            uint32_t afr[2][4];
#pragma unroll
            for (int mf = 0; mf < 2; mf++) {
                int m = warpM * 32 + mf * 16;
                afr[mf][0] = __float_as_uint(As[m + gID    ][kc + ct    ]);
                afr[mf][1] = __float_as_uint(As[m + gID + 8][kc + ct    ]);
                afr[mf][2] = __float_as_uint(As[m + gID    ][kc + ct + 4]);
                afr[mf][3] = __float_as_uint(As[m + gID + 8][kc + ct + 4]);
            }
#pragma unroll
            for (int nf = 0; nf < 8; nf++) {
                int n = warpN * 64 + nf * 8 + gID;
                uint32_t bfr[2];
                bfr[0] = __float_as_uint(Bs[kc + ct    ][n]);
                bfr[1] = __float_as_uint(Bs[kc + ct + 4][n]);
                mma_tf32(acc[0][nf], afr[0], bfr);
                mma_tf32(acc[1][nf], afr[1], bfr);
            }
        }
    }

#pragma unroll
    for (int mf = 0; mf < 2; mf++) {
        int r = bm + warpM * 32 + mf * 16 + gID;
#pragma unroll
        for (int nf = 0; nf < 8; nf++) {
            int cidx = bn + warpN * 64 + nf * 8 + ct * 2;
            float b0 = 0.f, b1 = 0.f;
            if (bias) { b0 = bias[cidx]; b1 = bias[cidx + 1]; }
            float2 v0 = make_float2(acc[mf][nf][0] + b0, acc[mf][nf][1] + b1);
            float2 v1 = make_float2(acc[mf][nf][2] + b0, acc[mf][nf][3] + b1);
            *(float2*)&C[(size_t)r * DD + cidx] = v0;
            *(float2*)&C[(size_t)(r + 8) * DD + cidx] = v1;
        }
    }
}

// ---------------------------------------------------------------------------
// Flash attention, tf32 MMA, pipelined.
// 64q tiles, 128 threads (4 warps, 16 q-rows each, full key range per warp).
// Ping-pong smem K/V buffers (dynamic); next-K prefetched during S, next-V
// during PV. P aliases the current K buffer. Q frags in regs (pre-scaled).
// MODE 0 (ress): direct output. MODE 1 (resq): split-KV over blockIdx.z,
// writes normalized partials + (m,l) for later merge.
// smem layout: Ks[2][64][68], Vs[2][64][72]  (71680 bytes)
// ---------------------------------------------------------------------------
#define KS_STRIDE 68
#define VS_STRIDE 72
#define KS_BUF (64*KS_STRIDE)
#define VS_BUF (64*VS_STRIDE)
#define SMEM_ATTN ((2*KS_BUF + 2*VS_BUF)*4)

template<int MODE>
__global__ __launch_bounds__(128) void attn_mma_kernel(
    const float* __restrict__ Qg, const float* __restrict__ Kg,
    const float* __restrict__ Vg, float* __restrict__ Og,
    float* __restrict__ Opart, float* __restrict__ Ml)
{
    extern __shared__ float sm[];
    float* Ksm = sm;                // [2][64][68]
    float* Vsm = sm + 2*KS_BUF;     // [2][64][72]

    const int tid = threadIdx.x;
    const int lid = tid & 31, w = tid >> 5;
    const int gID = lid >> 2, ct = lid & 3;
    const int q0 = blockIdx.x * 64;

    int b, h, f, qf, df = 1, t0, t1;
    if (MODE == 0) {
        int y = blockIdx.y;
        b = y / ((FF-1) * HH);
        int r = y % ((FF-1) * HH);
        f = 1 + r / HH;
        h = r % HH;
        qf = f;
        t0 = 0; t1 = SS / 64;
    } else {
        int y = blockIdx.y;
        b = y >> 3;
        h = y & 7;
        qf = 0; f = 0;
        df = g_df[b];
        int ntot = (SS / 64) * df;
        int sp = blockIdx.z;
        t0 = sp * ntot / NSPLIT;
        t1 = (sp + 1) * ntot / NSPLIT;
    }

    // Q fragments in registers (rows w*16+gID, +8), pre-scaled by 1/8
    uint32_t qa[8][4];
    {
        const int r0 = q0 + w * 16 + gID;
        const size_t base0 = ((size_t)(b*SS + r0    ) * FF + qf) * DD + h * CC;
        const size_t base1 = ((size_t)(b*SS + r0 + 8) * FF + qf) * DD + h * CC;
#pragma unroll
        for (int kc = 0; kc < 8; kc++) {
            qa[kc][0] = __float_as_uint(to_tf32(Qg[base0 + kc*8 + ct    ] * 0.125f));
            qa[kc][1] = __float_as_uint(to_tf32(Qg[base1 + kc*8 + ct    ] * 0.125f));
            qa[kc][2] = __float_as_uint(to_tf32(Qg[base0 + kc*8 + ct + 4] * 0.125f));
            qa[kc][3] = __float_as_uint(to_tf32(Qg[base1 + kc*8 + ct + 4] * 0.125f));
        }
    }

    float o[8][4];
#pragma unroll
    for (int nf = 0; nf < 8; nf++)
#pragma unroll
        for (int r = 0; r < 4; r++) o[nf][r] = 0.f;
    float m0 = -1e30f, m1 = -1e30f, l0 = 0.f, l1 = 0.f;

    // K/V tile load assignment: key = tid&63 (phase-friendly), half of c
    const int key   = tid & 63;
    const int chalf = (tid >> 6) * 32;

    // Global row base for a tile index kt (recomputed per use)
    auto row_of = [&](int kt) -> size_t {
        int kg = kt * 64 + key;
        int sk, fk;
        if (MODE == 0) { sk = kg; fk = f; }
        else           { sk = kg / df; fk = g_frames[b][kg - sk*df]; }
        return ((size_t)(b*SS + sk) * FF + fk) * DD + h * CC + chalf;
    };

    float4 kreg[8], vreg[8];
    {
        size_t r = row_of(t0);
#pragma unroll
        for (int u = 0; u < 8; u++) kreg[u] = *(const float4*)&Kg[r + u*4];
#pragma unroll
        for (int u = 0; u < 8; u++) vreg[u] = *(const float4*)&Vg[r + u*4];
    }

    const int pr0 = w * 16 + gID, pr1 = pr0 + 8;

    for (int kt = t0; kt < t1; kt++) {
        const int cur = kt & 1;
        float* Kb = Ksm + cur * KS_BUF;
        float* Vb = Vsm + cur * VS_BUF;

        // Store prefetched tile to smem (cvt to tf32, vectorized)
        {
            float* kd = Kb + key * KS_STRIDE + chalf;
            float* vd = Vb + key * VS_STRIDE + chalf;
#pragma unroll
            for (int u = 0; u < 8; u++) {
                float4 kc4 = make_float4(to_tf32(kreg[u].x), to_tf32(kreg[u].y),
                                         to_tf32(kreg[u].z), to_tf32(kreg[u].w));
                *(float4*)(kd + u*4) = kc4;
            }
#pragma unroll
            for (int u = 0; u < 8; u++) {
                float4 vc4 = make_float4(to_tf32(vreg[u].x), to_tf32(vreg[u].y),
                                         to_tf32(vreg[u].z), to_tf32(vreg[u].w));
                *(float4*)(vd + u*4) = vc4;
            }
        }
        __syncthreads();

        // Prefetch next K tile (latency hidden by S + softmax)
        if (kt + 1 < t1) {
            size_t r = row_of(kt + 1);
#pragma unroll
            for (int u = 0; u < 8; u++) kreg[u] = *(const float4*)&Kg[r + u*4];
        }

        // S = (Q*sc) K^T : A=Q rows, B=K^T (k=c, n=key); K stored [key][c]
        float s[8][4];
#pragma unroll
        for (int nf = 0; nf < 8; nf++)
#pragma unroll
            for (int r = 0; r < 4; r++) s[nf][r] = 0.f;
#pragma unroll
        for (int kc = 0; kc < 8; kc++) {
#pragma unroll
            for (int nf = 0; nf < 8; nf++) {
                uint32_t bfr[2];
                bfr[0] = __float_as_uint(Kb[(nf*8 + gID) * KS_STRIDE + kc*8 + ct    ]);
                bfr[1] = __float_as_uint(Kb[(nf*8 + gID) * KS_STRIDE + kc*8 + ct + 4]);
                mma_tf32(s[nf], qa[kc], bfr);
            }
        }

        // Online softmax (rows gID -> regs 0,1 and gID+8 -> regs 2,3)
        float mx0 = -1e30f, mx1 = -1e30f;
#pragma unroll
        for (int nf = 0; nf < 8; nf++) {
            mx0 = fmaxf(mx0, fmaxf(s[nf][0], s[nf][1]));
            mx1 = fmaxf(mx1, fmaxf(s[nf][2], s[nf][3]));
        }
        mx0 = fmaxf(mx0, __shfl_xor_sync(0xffffffffu, mx0, 1));
        mx0 = fmaxf(mx0, __shfl_xor_sync(0xffffffffu, mx0, 2));
        mx1 = fmaxf(mx1, __shfl_xor_sync(0xffffffffu, mx1, 1));
        mx1 = fmaxf(mx1, __shfl_xor_sync(0xffffffffu, mx1, 2));

        float m0n = fmaxf(m0, mx0), m1n = fmaxf(m1, mx1);
        float a0 = __expf(m0 - m0n), a1 = __expf(m1 - m1n);
        float s0 = 0.f, s1 = 0.f;
#pragma unroll
        for (int nf = 0; nf < 8; nf++) {
            s[nf][0] = __expf(s[nf][0] - m0n);
            s[nf][1] = __expf(s[nf][1] - m0n);
            s[nf][2] = __expf(s[nf][2] - m1n);
            s[nf][3] = __expf(s[nf][3] - m1n);
            s0 += s[nf][0] + s[nf][1];
            s1 += s[nf][2] + s[nf][3];
        }
        s0 += __shfl_xor_sync(0xffffffffu, s0, 1);
        s0 += __shfl_xor_sync(0xffffffffu, s0, 2);
        s1 += __shfl_xor_sync(0xffffffffu, s1, 1);
        s1 += __shfl_xor_sync(0xffffffffu, s1, 2);
        l0 = l0 * a0 + s0; m0 = m0n;
        l1 = l1 * a1 + s1; m1 = m1n;
#pragma unroll
        for (int nf = 0; nf < 8; nf++) {
            o[nf][0] *= a0; o[nf][1] *= a0;
            o[nf][2] *= a1; o[nf][3] *= a1;
        }

        __syncthreads();   // all warps done reading Kb as K

        // Store P (tf32) into Kb as [q][key]; own rows only
#pragma unroll
        for (int nf = 0; nf < 8; nf++) {
            int col = nf * 8 + ct * 2;
            *(float2*)&Kb[pr0 * KS_STRIDE + col] =
                make_float2(to_tf32(s[nf][0]), to_tf32(s[nf][1]));
            *(float2*)&Kb[pr1 * KS_STRIDE + col] =
                make_float2(to_tf32(s[nf][2]), to_tf32(s[nf][3]));
        }

        // Prefetch next V tile (latency hidden by PV)
        if (kt + 1 < t1) {
            size_t r = row_of(kt + 1);
#pragma unroll
            for (int u = 0; u < 8; u++) vreg[u] = *(const float4*)&Vg[r + u*4];
        }

        // O += P @ V : A=P rows, B=V (k=key, n=c); V stored [key][c]
#pragma unroll
        for (int kc = 0; kc < 8; kc++) {
            uint32_t pa[4];
            pa[0] = __float_as_uint(Kb[pr0 * KS_STRIDE + kc*8 + ct    ]);
            pa[1] = __float_as_uint(Kb[pr1 * KS_STRIDE + kc*8 + ct    ]);
            pa[2] = __float_as_uint(Kb[pr0 * KS_STRIDE + kc*8 + ct + 4]);
            pa[3] = __float_as_uint(Kb[pr1 * KS_STRIDE + kc*8 + ct + 4]);
#pragma unroll
            for (int nf = 0; nf < 8; nf++) {
                uint32_t bfr[2];
                bfr[0] = __float_as_uint(Vb[(kc*8 + ct    ) * VS_STRIDE + nf*8 + gID]);
                bfr[1] = __float_as_uint(Vb[(kc*8 + ct + 4) * VS_STRIDE + nf*8 + gID]);
                mma_tf32(o[nf], pa, bfr);
            }
        }
    }

    // Epilogue
    const float inv0 = 1.0f / l0, inv1 = 1.0f / l1;
    const int r0 = q0 + w * 16 + gID;
    if (MODE == 0) {
        const size_t ob0 = ((size_t)(b*SS + r0    ) * FF + f) * DD + h * CC;
        const size_t ob1 = ((size_t)(b*SS + r0 + 8) * FF + f) * DD + h * CC;
#pragma unroll
        for (int nf = 0; nf < 8; nf++) {
            int col = nf * 8 + ct * 2;
            *(float2*)&Og[ob0 + col] = make_float2(o[nf][0] * inv0, o[nf][1] * inv0);
            *(float2*)&Og[ob1 + col] = make_float2(o[nf][2] * inv1, o[nf][3] * inv1);
        }
    } else {
        const int y = blockIdx.y, sp = blockIdx.z;
        const size_t pb0 = ((size_t)(sp*(BB*HH) + y) * SS + r0    ) * CC;
        const size_t pb1 = ((size_t)(sp*(BB*HH) + y) * SS + r0 + 8) * CC;
#pragma unroll
        for (int nf = 0; nf < 8; nf++) {
            int col = nf * 8 + ct * 2;
            *(float2*)&Opart[pb0 + col] = make_float2(o[nf][0] * inv0, o[nf][1] * inv0);
            *(float2*)&Opart[pb1 + col] = make_float2(o[nf][2] * inv1, o[nf][3] * inv1);
        }
        if (ct == 0) {
            size_t mb = ((size_t)(sp*(BB*HH) + y) * SS + r0) * 2;
            Ml[mb + 0] = m0; Ml[mb + 1] = l0;
            Ml[mb + CC/4] = 0.f; // placeholder avoided; see below
        }
        if (ct == 0) {
            size_t mb1 = ((size_t)(sp*(BB*HH) + y) * SS + r0 + 8) * 2;
            Ml[mb1 + 0] = m1; Ml[mb1 + 1] = l1;
        }
    }
}

// ---------------------------------------------------------------------------
// Merge resq split partials into g_att frame 0.
// One thread per (y, q, c4): float4 over C.
// ---------------------------------------------------------------------------
__global__ __launch_bounds__(256) void merge_resq_kernel(float* __restrict__ att)
{
    int idx = blockIdx.x * 256 + threadIdx.x;           // over 16*576*16
    if (idx >= BB*HH*SS*(CC/4)) return;
    int c4 = idx & 15;
    int q  = (idx >> 4) % SS;
    int y  = idx / (16 * SS);

    float m[NSPLIT], l[NSPLIT];
    float mmax = -1e30f;
#pragma unroll
    for (int s = 0; s < NSPLIT; s++) {
        size_t mb = ((size_t)(s*(BB*HH) + y) * SS + q) * 2;
        m[s] = g_ml[mb]; l[s] = g_ml[mb + 1];
        mmax = fmaxf(mmax, m[s]);
    }
    float4 acc = make_float4(0.f, 0.f, 0.f, 0.f);
    float wsum = 0.f;
#pragma unroll
    for (int s = 0; s < NSPLIT; s++) {
        float wgt = __expf(m[s] - mmax) * l[s];
        const float4 ov = *(const float4*)&g_opart[(((size_t)(s*(BB*HH) + y) * SS + q) * CC) + c4*4];
        acc.x += wgt * ov.x; acc.y += wgt * ov.y;
        acc.z += wgt * ov.z; acc.w += wgt * ov.w;
        wsum += wgt;
    }
    float inv = 1.0f / wsum;
    int b = y >> 3, h = y & 7;
    float4 r = make_float4(acc.x*inv, acc.y*inv, acc.z*inv, acc.w*inv);
    *(float4*)&att[((size_t)(b*SS + q) * FF + 0) * DD + h*CC + c4*4] = r;
}

// ---------------------------------------------------------------------------
extern "C" void kernel_launch(void* const* d_in, const int* in_sizes, int n_in,
                              void* d_out, int out_size)
{
    const float* x    = (const float*)d_in[0];
    const int*   mask = (const int*)  d_in[1];
    const float* Wq   = (const float*)d_in[2];
    const float* Wk   = (const float*)d_in[3];
    const float* Wv   = (const float*)d_in[4];
    const float* Wout = (const float*)d_in[5];
    const float* bout = (const float*)d_in[6];
    float* out = (float*)d_out;

    float *q, *k, *v, *att, *opart, *ml;
    cudaGetSymbolAddress((void**)&q,     g_q);
    cudaGetSymbolAddress((void**)&k,     g_k);
    cudaGetSymbolAddress((void**)&v,     g_v);
    cudaGetSymbolAddress((void**)&att,   g_att);
    cudaGetSymbolAddress((void**)&opart, g_opart);
    cudaGetSymbolAddress((void**)&ml,    g_ml);

    static bool attr_set = false;
    if (!attr_set) {
        cudaFuncSetAttribute(attn_mma_kernel<0>,
            cudaFuncAttributeMaxDynamicSharedMemorySize, SMEM_ATTN);
        cudaFuncSetAttribute(attn_mma_kernel<1>,
            cudaFuncAttributeMaxDynamicSharedMemorySize, SMEM_ATTN);
        attr_set = true;
    }

    build_frames_kernel<<<1, 32>>>(mask);

    // Fused QKV projections (grid.z selects weight)
    gemm_tf32_kernel<<<dim3(MROWS/128, DD/128, 3), 256>>>(
        x, Wq, Wk, Wv, q, k, v, nullptr);

    // ress: per-frame self attention, frames 1..15
    attn_mma_kernel<0><<<dim3(SS/64, BB*(FF-1)*HH, 1), 128, SMEM_ATTN>>>(
        q, k, v, att, nullptr, nullptr);
    // resq: split-KV over NSPLIT
    attn_mma_kernel<1><<<dim3(SS/64, BB*HH, NSPLIT), 128, SMEM_ATTN>>>(
        q, k, v, att, opart, ml);
    merge_resq_kernel<<<(BB*HH*SS*(CC/4) + 255)/256, 256>>>(att);

    // Output projection + bias
    gemm_tf32_kernel<<<dim3(MROWS/128, DD/128, 1), 256>>>(
        att, Wout, Wout, Wout, out, out, out, bout);
}